// round 3
// baseline (speedup 1.0000x reference)
#include <cuda_runtime.h>

#define B_  16
#define S_  128
#define T_  128
#define ST_ 127
#define E_  256
#define H_  512
#define H2_ 1024
#define H3_ 1536
#define KD_ 1280
#define KO_ 1792
#define V_  32000

// ---------------- scratch (device globals; no allocation allowed) ----------------
__device__ float g_emb    [B_*S_*E_];
__device__ float g_emb_rev[B_*S_*E_];
__device__ float g_emb_in [ST_*B_*E_];
__device__ float g_GI_f   [B_*S_*H3_];
__device__ float g_GI_b   [B_*S_*H3_];
__device__ float g_GIe    [ST_*B_*H3_];
__device__ float g_enc_out[B_*S_*H2_];
__device__ float g_out_bR [B_*S_*H_];
__device__ float g_encP   [B_*S_*H_];
__device__ float g_feat   [ST_*B_*KO_];   // [t*16+b][ h(512) | ctx(1024) | e(256) ]
__device__ float g_hf  [2*B_*H_];
__device__ float g_hb  [2*B_*H_];
__device__ float g_hdec[2*B_*H_];

// ---------------- helpers ----------------
__device__ __forceinline__ float sigf(float x) { return 1.f / (1.f + expf(-x)); }

__device__ __forceinline__ unsigned long long f2pack(float a, float b) {
    unsigned long long r;
    asm("mov.b64 %0, {%1, %2};" : "=l"(r) : "r"(__float_as_uint(a)), "r"(__float_as_uint(b)));
    return r;
}
__device__ __forceinline__ void f2fma(unsigned long long& d, unsigned long long a, unsigned long long b) {
    asm("fma.rn.f32x2 %0, %1, %2, %0;" : "+l"(d) : "l"(a), "l"(b));
}
__device__ __forceinline__ float2 f2unpack(unsigned long long v) {
    unsigned lo, hi;
    asm("mov.b64 {%0, %1}, %2;" : "=r"(lo), "=r"(hi) : "l"(v));
    return make_float2(__uint_as_float(lo), __uint_as_float(hi));
}

// ---------------- gathers + init ----------------
__global__ void k_gather(const int* __restrict__ src, const int* __restrict__ len,
                         const int* __restrict__ tgt,
                         const float* __restrict__ enc_emb, const float* __restrict__ dec_emb)
{
    const int total = B_*S_*E_;
    for (int i = blockIdx.x*blockDim.x + threadIdx.x; i < total; i += gridDim.x*blockDim.x) {
        int e = i % E_;
        int s = (i / E_) % S_;
        int b = i / (E_*S_);
        int L = len[b];
        g_emb[i] = enc_emb[(size_t)src[b*S_+s]*E_ + e];
        int r = (s < L) ? (L-1-s) : s;
        g_emb_rev[i] = enc_emb[(size_t)src[b*S_+r]*E_ + e];
        if (s < ST_) {
            float v = dec_emb[(size_t)tgt[b*T_+s]*E_ + e];
            size_t n = (size_t)s*B_ + b;
            g_emb_in[n*E_ + e] = v;
            g_feat[n*KO_ + (H_+H2_) + e] = v;    // e_t section of logit features
        }
        if (i < 2*B_*H_) { g_hf[i] = 0.f; g_hb[i] = 0.f; }
    }
}

// ---------------- generic tiled GEMM: C[m][n] = sum_k A[m][k]*W[n][k] (+bias[n]) ----------------
// A: [M,K] (lda=K). W: [N, ldw] row-major, uses first K cols. N must be multiple of 128.
// remap!=0: C row m -> d_out row (b*127 + t) with b=m%16, t=m/16 (logits transpose).
__global__ __launch_bounds__(256, 2)
void k_gemm(const float* __restrict__ A, const float* __restrict__ W,
            const float* __restrict__ bias, float* __restrict__ C,
            int M, int N, int K, int ldw, int remap)
{
    __shared__ float As[16][132];
    __shared__ float Bs[16][132];
    const int tid = threadIdx.x;
    const int tx = tid & 15, ty = tid >> 4;
    const int m0 = blockIdx.y * 128;
    const int n0 = blockIdx.x * 128;
    const int lr = tid >> 2;          // 0..63
    const int lc = (tid & 3) * 4;     // 0,4,8,12

    unsigned long long acc[8][4];
    #pragma unroll
    for (int i = 0; i < 8; i++)
        #pragma unroll
        for (int j = 0; j < 4; j++) acc[i][j] = 0ULL;

    for (int k0 = 0; k0 < K; k0 += 16) {
        #pragma unroll
        for (int h = 0; h < 2; h++) {
            int m = m0 + lr + h*64;
            float4 v = (m < M) ? *(const float4*)(A + (size_t)m*K + k0 + lc)
                               : make_float4(0.f,0.f,0.f,0.f);
            As[lc+0][lr+h*64] = v.x; As[lc+1][lr+h*64] = v.y;
            As[lc+2][lr+h*64] = v.z; As[lc+3][lr+h*64] = v.w;
        }
        #pragma unroll
        for (int h = 0; h < 2; h++) {
            int n = n0 + lr + h*64;
            float4 v = *(const float4*)(W + (size_t)n*ldw + k0 + lc);
            Bs[lc+0][lr+h*64] = v.x; Bs[lc+1][lr+h*64] = v.y;
            Bs[lc+2][lr+h*64] = v.z; Bs[lc+3][lr+h*64] = v.w;
        }
        __syncthreads();
        #pragma unroll
        for (int k = 0; k < 16; k++) {
            float4 a0 = *(const float4*)&As[k][ty*8];
            float4 a1 = *(const float4*)&As[k][ty*8+4];
            float4 b0 = *(const float4*)&Bs[k][tx*8];
            float4 b1 = *(const float4*)&Bs[k][tx*8+4];
            float ra[8] = {a0.x,a0.y,a0.z,a0.w,a1.x,a1.y,a1.z,a1.w};
            unsigned long long bp[4];
            bp[0] = f2pack(b0.x, b0.y); bp[1] = f2pack(b0.z, b0.w);
            bp[2] = f2pack(b1.x, b1.y); bp[3] = f2pack(b1.z, b1.w);
            #pragma unroll
            for (int i = 0; i < 8; i++) {
                unsigned long long ap = f2pack(ra[i], ra[i]);
                f2fma(acc[i][0], ap, bp[0]);
                f2fma(acc[i][1], ap, bp[1]);
                f2fma(acc[i][2], ap, bp[2]);
                f2fma(acc[i][3], ap, bp[3]);
            }
        }
        __syncthreads();
    }

    #pragma unroll
    for (int i = 0; i < 8; i++) {
        int m = m0 + ty*8 + i;
        if (m >= M) continue;
        float* crow = remap ? (C + ((size_t)(m & 15) * ST_ + (m >> 4)) * N)
                            : (C + (size_t)m * N);
        int nc = n0 + tx*8;
        #pragma unroll
        for (int j = 0; j < 4; j++) {
            float2 v = f2unpack(acc[i][j]);
            float c0 = v.x, c1 = v.y;
            if (bias) { c0 += bias[nc+2*j]; c1 += bias[nc+2*j+1]; }
            crow[nc+2*j]   = c0;
            crow[nc+2*j+1] = c1;
        }
    }
}

// ---------------- encoder GRU step (both directions): h-side GEMV + gates ----------------
__global__ void k_enc_step(const float* __restrict__ W_hh_f, const float* __restrict__ b_hh_f,
                           const float* __restrict__ W_hh_b, const float* __restrict__ b_hh_b,
                           const int* __restrict__ len, int t)
{
    const int dir = blockIdx.y;
    const int tid = threadIdx.x;
    const int b = tid & 15;
    const int j = blockIdx.x * 16 + (tid >> 4);

    const float* Whh = dir ? W_hh_b : W_hh_f;
    const float* bhh = dir ? b_hh_b : b_hh_f;
    float* hbase = dir ? g_hb : g_hf;
    const float* hrow  = hbase + (t & 1)     * (B_*H_) + b*H_;
    float*       hnrow = hbase + ((t+1) & 1) * (B_*H_) + b*H_;
    const float* GI = (dir ? g_GI_b : g_GI_f) + ((size_t)(b*S_ + t)) * H3_;

    const float* Wr = Whh + (size_t)j * H_;
    const float* Wz = Wr + (size_t)H_*H_;
    const float* Wn = Wz + (size_t)H_*H_;

    float ar = 0.f, az = 0.f, an = 0.f;
    #pragma unroll 4
    for (int k = 0; k < H_; k += 4) {
        float4 hv = *(const float4*)(hrow + k);
        float4 wr = *(const float4*)(Wr + k);
        float4 wz = *(const float4*)(Wz + k);
        float4 wn = *(const float4*)(Wn + k);
        ar = fmaf(hv.x,wr.x, fmaf(hv.y,wr.y, fmaf(hv.z,wr.z, fmaf(hv.w,wr.w, ar))));
        az = fmaf(hv.x,wz.x, fmaf(hv.y,wz.y, fmaf(hv.z,wz.z, fmaf(hv.w,wz.w, az))));
        an = fmaf(hv.x,wn.x, fmaf(hv.y,wn.y, fmaf(hv.z,wn.z, fmaf(hv.w,wn.w, an))));
    }
    float hr = ar + bhh[j], hz = az + bhh[H_+j], hn = an + bhh[2*H_+j];
    float r = sigf(GI[j]      + hr);
    float z = sigf(GI[H_+j]   + hz);
    float n = tanhf(GI[2*H_+j] + r*hn);
    float hold = hrow[j];
    float hnew = (1.f - z)*n + z*hold;
    bool valid = t < len[b];
    hnrow[j] = valid ? hnew : hold;
    float o = valid ? hnew : 0.f;
    if (dir == 0) g_enc_out[((size_t)(b*S_+t))*H2_ + j] = o;
    else          g_out_bR [((size_t)(b*S_+t))*H_  + j] = o;
}

// ---------------- scatter backward outputs into enc_out (un-reverse) ----------------
__global__ void k_outbw(const int* __restrict__ len)
{
    int i = blockIdx.x*blockDim.x + threadIdx.x;
    if (i >= B_*S_*H_) return;
    int j = i % H_;
    int s = (i / H_) % S_;
    int b = i / (H_*S_);
    int L = len[b];
    int r = (s < L) ? (L-1-s) : s;
    g_enc_out[((size_t)(b*S_+s))*H2_ + H_ + j] = g_out_bR[((size_t)(b*S_+r))*H_ + j];
}

// ---------------- bridge: h0_dec = tanh([h_f,h_b] @ bridge_W.T + b) ----------------
__global__ void k_bridge(const float* __restrict__ bridge_W, const float* __restrict__ bridge_b)
{
    const int tid = threadIdx.x;
    const int b = tid & 15;
    const int j = blockIdx.x * 16 + (tid >> 4);
    const float* Wrow = bridge_W + (size_t)j * H2_;
    const float* hf = g_hf + b*H_;   // final state lands in parity buffer 0
    const float* hb = g_hb + b*H_;
    float acc = 0.f;
    #pragma unroll 4
    for (int k = 0; k < H_; k += 4) {
        float4 h = *(const float4*)(hf + k);
        float4 w = *(const float4*)(Wrow + k);
        acc = fmaf(h.x,w.x, fmaf(h.y,w.y, fmaf(h.z,w.z, fmaf(h.w,w.w, acc))));
    }
    #pragma unroll 4
    for (int k = 0; k < H_; k += 4) {
        float4 h = *(const float4*)(hb + k);
        float4 w = *(const float4*)(Wrow + H_ + k);
        acc = fmaf(h.x,w.x, fmaf(h.y,w.y, fmaf(h.z,w.z, fmaf(h.w,w.w, acc))));
    }
    g_hdec[b*H_ + j] = tanhf(acc + bridge_b[j]);
}

// ---------------- fused attention per decode step: dp, energy, softmax, ctx ----------------
__global__ void k_attn(const float* __restrict__ Wa_dec, const float* __restrict__ Wv,
                       const int* __restrict__ src, int t)
{
    __shared__ float hsm[H_];
    __shared__ float dps[H_];
    __shared__ float wvs[H_];
    __shared__ float esm[S_];
    __shared__ float sinv;
    const int b = blockIdx.x;
    const int tid = threadIdx.x;
    const int lane = tid & 31, w = tid >> 5;

    const float* hrow = g_hdec + (t & 1)*(B_*H_) + b*H_;
    for (int k = tid; k < H_; k += 256) { hsm[k] = hrow[k]; wvs[k] = Wv[k]; }
    __syncthreads();

    // dp[j] = h . Wa_dec[j]
    for (int jj = w*64; jj < w*64 + 64; jj++) {
        const float* wa = Wa_dec + (size_t)jj * H_;
        float s = 0.f;
        #pragma unroll
        for (int i = 0; i < 16; i++) { int k = lane + 32*i; s = fmaf(wa[k], hsm[k], s); }
        #pragma unroll
        for (int o = 16; o; o >>= 1) s += __shfl_xor_sync(0xffffffffu, s, o);
        if (lane == 0) dps[jj] = s;
    }
    __syncthreads();

    // energy[s] = sum_j tanh(encP[b,s,j] + dp[j]) * Wv[j], masked
    const float* ePb = g_encP + (size_t)b*S_*H_;
    for (int s0 = w; s0 < S_; s0 += 8) {
        const float* er = ePb + (size_t)s0 * H_;
        float acc = 0.f;
        #pragma unroll
        for (int i = 0; i < 16; i++) {
            int k = lane + 32*i;
            acc = fmaf(tanhf(er[k] + dps[k]), wvs[k], acc);
        }
        #pragma unroll
        for (int o = 16; o; o >>= 1) acc += __shfl_xor_sync(0xffffffffu, acc, o);
        if (lane == 0) esm[s0] = (src[b*S_ + s0] != 0) ? acc : -1e9f;
    }
    __syncthreads();

    if (w == 0) {
        float v[4]; float m = -1e30f;
        #pragma unroll
        for (int i = 0; i < 4; i++) { v[i] = esm[lane + 32*i]; m = fmaxf(m, v[i]); }
        #pragma unroll
        for (int o = 16; o; o >>= 1) m = fmaxf(m, __shfl_xor_sync(0xffffffffu, m, o));
        float sum = 0.f;
        #pragma unroll
        for (int i = 0; i < 4; i++) { v[i] = expf(v[i] - m); sum += v[i]; }
        #pragma unroll
        for (int o = 16; o; o >>= 1) sum += __shfl_xor_sync(0xffffffffu, sum, o);
        #pragma unroll
        for (int i = 0; i < 4; i++) esm[lane + 32*i] = v[i];
        if (lane == 0) sinv = 1.f / sum;
    }
    __syncthreads();

    // ctx[j] = sum_s attn[s] * enc_out[b,s,j]; write into feat ctx section
    const float* eo = g_enc_out + (size_t)b*S_*H2_;
    const int j4 = tid * 4;
    float c0=0.f,c1=0.f,c2=0.f,c3=0.f;
    for (int s0 = 0; s0 < S_; s0++) {
        float a = esm[s0];
        float4 v = *(const float4*)(eo + (size_t)s0*H2_ + j4);
        c0 = fmaf(a, v.x, c0); c1 = fmaf(a, v.y, c1);
        c2 = fmaf(a, v.z, c2); c3 = fmaf(a, v.w, c3);
    }
    float inv = sinv;
    *(float4*)(g_feat + ((size_t)(t*B_ + b))*KO_ + H_ + j4) =
        make_float4(c0*inv, c1*inv, c2*inv, c3*inv);
}

// ---------------- decoder GRU step: gi(ctx part) + gh + gates ----------------
__global__ void k_dec(const float* __restrict__ W_ih_d, const float* __restrict__ W_hh_d,
                      const float* __restrict__ b_hh_d, int t)
{
    const int tid = threadIdx.x;
    const int b = tid & 15;
    const int j = blockIdx.x * 16 + (tid >> 4);
    const size_t n = (size_t)t*B_ + b;

    const float* gi = g_GIe + n * H3_;
    float air = gi[j], aiz = gi[H_+j], ain = gi[2*H_+j];

    const float* xr = g_feat + n*KO_ + H_;                 // ctx (1024)
    const float* Wr = W_ih_d + (size_t)j        * KD_ + E_;
    const float* Wz = W_ih_d + (size_t)(H_+j)   * KD_ + E_;
    const float* Wn = W_ih_d + (size_t)(2*H_+j) * KD_ + E_;
    #pragma unroll 4
    for (int k = 0; k < H2_; k += 4) {
        float4 x  = *(const float4*)(xr + k);
        float4 wr = *(const float4*)(Wr + k);
        float4 wz = *(const float4*)(Wz + k);
        float4 wn = *(const float4*)(Wn + k);
        air = fmaf(x.x,wr.x, fmaf(x.y,wr.y, fmaf(x.z,wr.z, fmaf(x.w,wr.w, air))));
        aiz = fmaf(x.x,wz.x, fmaf(x.y,wz.y, fmaf(x.z,wz.z, fmaf(x.w,wz.w, aiz))));
        ain = fmaf(x.x,wn.x, fmaf(x.y,wn.y, fmaf(x.z,wn.z, fmaf(x.w,wn.w, ain))));
    }

    const float* hrow = g_hdec + (t & 1)*(B_*H_) + b*H_;
    const float* Vr = W_hh_d + (size_t)j * H_;
    const float* Vz = Vr + (size_t)H_*H_;
    const float* Vn = Vz + (size_t)H_*H_;
    float ahr = 0.f, ahz = 0.f, ahn = 0.f;
    #pragma unroll 4
    for (int k = 0; k < H_; k += 4) {
        float4 h  = *(const float4*)(hrow + k);
        float4 wr = *(const float4*)(Vr + k);
        float4 wz = *(const float4*)(Vz + k);
        float4 wn = *(const float4*)(Vn + k);
        ahr = fmaf(h.x,wr.x, fmaf(h.y,wr.y, fmaf(h.z,wr.z, fmaf(h.w,wr.w, ahr))));
        ahz = fmaf(h.x,wz.x, fmaf(h.y,wz.y, fmaf(h.z,wz.z, fmaf(h.w,wz.w, ahz))));
        ahn = fmaf(h.x,wn.x, fmaf(h.y,wn.y, fmaf(h.z,wn.z, fmaf(h.w,wn.w, ahn))));
    }
    ahr += b_hh_d[j]; ahz += b_hh_d[H_+j]; ahn += b_hh_d[2*H_+j];

    float r = sigf(air + ahr);
    float z = sigf(aiz + ahz);
    float nn = tanhf(ain + r*ahn);
    float hold = hrow[j];
    float hnew = (1.f - z)*nn + z*hold;

    g_hdec[((t+1) & 1)*(B_*H_) + b*H_ + j] = hnew;
    g_feat[n*KO_ + j] = hnew;
}

// ---------------- launch ----------------
extern "C" void kernel_launch(void* const* d_in, const int* in_sizes, int n_in,
                              void* d_out, int out_size)
{
    const int*   src      = (const int*)d_in[0];
    const int*   len      = (const int*)d_in[1];
    const int*   tgt      = (const int*)d_in[2];
    const float* enc_emb  = (const float*)d_in[3];
    const float* W_ih_f   = (const float*)d_in[4];
    const float* W_hh_f   = (const float*)d_in[5];
    const float* b_ih_f   = (const float*)d_in[6];
    const float* b_hh_f   = (const float*)d_in[7];
    const float* W_ih_b   = (const float*)d_in[8];
    const float* W_hh_b   = (const float*)d_in[9];
    const float* b_ih_b   = (const float*)d_in[10];
    const float* b_hh_b   = (const float*)d_in[11];
    const float* bridge_W = (const float*)d_in[12];
    const float* bridge_b = (const float*)d_in[13];
    const float* dec_emb  = (const float*)d_in[14];
    const float* Wa_enc   = (const float*)d_in[15];
    const float* Wa_dec   = (const float*)d_in[16];
    const float* Wv       = (const float*)d_in[17];
    const float* W_ih_d   = (const float*)d_in[18];
    const float* W_hh_d   = (const float*)d_in[19];
    const float* b_ih_d   = (const float*)d_in[20];
    const float* b_hh_d   = (const float*)d_in[21];
    const float* out_W    = (const float*)d_in[22];
    const float* out_b    = (const float*)d_in[23];
    float* out = (float*)d_out;

    float* p_emb     = nullptr; cudaGetSymbolAddress((void**)&p_emb,     g_emb);
    float* p_emb_rev = nullptr; cudaGetSymbolAddress((void**)&p_emb_rev, g_emb_rev);
    float* p_emb_in  = nullptr; cudaGetSymbolAddress((void**)&p_emb_in,  g_emb_in);
    float* p_GI_f    = nullptr; cudaGetSymbolAddress((void**)&p_GI_f,    g_GI_f);
    float* p_GI_b    = nullptr; cudaGetSymbolAddress((void**)&p_GI_b,    g_GI_b);
    float* p_GIe     = nullptr; cudaGetSymbolAddress((void**)&p_GIe,     g_GIe);
    float* p_enc_out = nullptr; cudaGetSymbolAddress((void**)&p_enc_out, g_enc_out);
    float* p_encP    = nullptr; cudaGetSymbolAddress((void**)&p_encP,    g_encP);
    float* p_feat    = nullptr; cudaGetSymbolAddress((void**)&p_feat,    g_feat);

    // 1. gathers (emb, emb_rev, dec emb -> feat e-section) + zero h0
    k_gather<<<512, 256>>>(src, len, tgt, enc_emb, dec_emb);

    // 2. input-side gate GEMMs (parallel over all timesteps)
    k_gemm<<<dim3(H3_/128, (B_*S_)/128), 256>>>(p_emb,     W_ih_f, b_ih_f, p_GI_f, B_*S_,  H3_, E_, E_,  0);
    k_gemm<<<dim3(H3_/128, (B_*S_)/128), 256>>>(p_emb_rev, W_ih_b, b_ih_b, p_GI_b, B_*S_,  H3_, E_, E_,  0);
    k_gemm<<<dim3(H3_/128, (ST_*B_+127)/128), 256>>>(p_emb_in, W_ih_d, b_ih_d, p_GIe, ST_*B_, H3_, E_, KD_, 0);

    // 3. encoder recurrence (fwd+bwd concurrently per step)
    for (int t = 0; t < S_; t++)
        k_enc_step<<<dim3(H_/16, 2), 256>>>(W_hh_f, b_hh_f, W_hh_b, b_hh_b, len, t);

    // 4. un-reverse backward outputs, bridge, encoder projection
    k_outbw<<<(B_*S_*H_)/256, 256>>>(len);
    k_bridge<<<H_/16, 256>>>(bridge_W, bridge_b);
    k_gemm<<<dim3(H_/128, (B_*S_)/128), 256>>>(p_enc_out, Wa_enc, nullptr, p_encP, B_*S_, H_, H2_, H2_, 0);

    // 5. decoder recurrence
    for (int t = 0; t < ST_; t++) {
        k_attn<<<B_, 256>>>(Wa_dec, Wv, src, t);
        k_dec<<<H_/16, 256>>>(W_ih_d, W_hh_d, b_hh_d, t);
    }

    // 6. output projection (dominant GEMM), rows remapped to [B, 127, V]
    k_gemm<<<dim3(V_/128, (ST_*B_+127)/128), 256>>>(p_feat, out_W, out_b, out, ST_*B_, V_, KO_, KO_, 1);
}